// round 7
// baseline (speedup 1.0000x reference)
#include <cuda_runtime.h>

#define Bn 16
#define Sn 16
#define Wn 32
#define Hn 512
#define Vn 32000
#define EXTRA 100
#define Tn 64
#define BOSTOK 1
#define SW 512          // Sn*Wn
#define VEXT 32100
#define G3H 1536

// ---------------- scratch (device globals; no allocation) ----------------
__device__ float g_wa_pre[Bn*SW*Hn];     // 16.8 MB
__device__ float g_sa_pre[Bn*Sn*Hn];
__device__ float g_x[Bn*Hn];
__device__ float g_dqw[Bn*Hn];
__device__ float g_dqs[Bn*Hn];
__device__ float g_scw[Bn*SW];
__device__ float g_resc[Bn*SW];
__device__ float g_ctx[Bn*Hn];
__device__ float g_gh[Bn*G3H];
__device__ float g_gi[Bn*G3H];
__device__ float g_selh[Bn*Hn];
__device__ float g_h[2][Bn*Hn];
__device__ float g_logits[(size_t)Bn*Vn]; // 2 MB

// ---------------- helpers ----------------
__device__ __forceinline__ float fast_tanh(float x) {
    float ax = fabsf(x);
    float t = __expf(-2.0f * ax);
    float r = (1.0f - t) / (1.0f + t);
    return copysignf(r, x);
}
__device__ __forceinline__ float fast_sigm(float x) {
    return 1.0f / (1.0f + __expf(-x));
}
__device__ __forceinline__ float warp_sum(float v) {
#pragma unroll
    for (int o = 16; o; o >>= 1) v += __shfl_xor_sync(0xffffffffu, v, o);
    return v;
}

// ---------------- one-time: pre = A @ W^T + b  (rows x 512, K=512) ----------
// block: 256 thr (8 warps), 16 A-rows in smem; warp holds 4 weight rows in regs
__global__ __launch_bounds__(256) void k_pre(const float* __restrict__ A,
                                             const float* __restrict__ Wt,
                                             const float* __restrict__ bias,
                                             int dst_sel)
{
    float* outp = dst_sel ? g_sa_pre : g_wa_pre;
    __shared__ float sh[16 * Hn];
    int r0 = blockIdx.x * 16;
    const float4* A4 = (const float4*)(A + (size_t)r0 * Hn);
    float4* sh4 = (float4*)sh;
    for (int i = threadIdx.x; i < 16 * Hn / 4; i += 256) sh4[i] = A4[i];
    __syncthreads();
    int w = threadIdx.x >> 5, lane = threadIdx.x & 31;
    const float4* W4 = (const float4*)Wt;
    for (int g = w; g < 128; g += 8) {
        int o0 = g * 4;
        float4 wr[4][4];
#pragma unroll
        for (int j = 0; j < 4; j++)
#pragma unroll
            for (int k = 0; k < 4; k++)
                wr[j][k] = W4[(size_t)(o0 + j) * (Hn / 4) + k * 32 + lane];
        for (int r = 0; r < 16; r++) {
            float4 a[4];
#pragma unroll
            for (int k = 0; k < 4; k++) a[k] = sh4[r * (Hn / 4) + k * 32 + lane];
            float acc[4];
#pragma unroll
            for (int j = 0; j < 4; j++) {
                float s_ = 0.f;
#pragma unroll
                for (int k = 0; k < 4; k++)
                    s_ += wr[j][k].x * a[k].x + wr[j][k].y * a[k].y +
                          wr[j][k].z * a[k].z + wr[j][k].w * a[k].w;
                acc[j] = s_;
            }
#pragma unroll
            for (int o = 16; o; o >>= 1)
#pragma unroll
                for (int j = 0; j < 4; j++)
                    acc[j] += __shfl_xor_sync(0xffffffffu, acc[j], o);
            if (lane < 4)
                outp[(size_t)(r0 + r) * Hn + o0 + lane] = acc[lane] + bias[o0 + lane];
        }
    }
}

__global__ void k_init_h(const float* __restrict__ src) {
    int i = blockIdx.x * 256 + threadIdx.x;
    if (i < Bn * Hn) g_h[0][i] = src[i];
}
__global__ void k_out_h(float* __restrict__ out) {
    int i = blockIdx.x * 256 + threadIdx.x;
    if (i < Bn * Hn) out[(size_t)Bn * Tn * VEXT + i] = g_h[0][i];
}

// ---------------- per-step K1: x, dq_w, dq_s, gh ----------------
// grid (321, 16): bx<320 -> warp-per-dot (2560 outputs/b); bx==320 -> x gather
__global__ __launch_bounds__(256) void k_step1(
    int t, const int* __restrict__ target, const float* __restrict__ emb,
    const float* __restrict__ wa_w2, const float* __restrict__ wa_b2,
    const float* __restrict__ sa_w2, const float* __restrict__ sa_b2,
    const float* __restrict__ w_hh, const float* __restrict__ b_hh)
{
    int b = blockIdx.y;
    const float* hprev = g_h[t & 1];
    if (blockIdx.x == 320) {
        int tok = (t == 0) ? BOSTOK : target[b * Tn + t - 1];
        if (tok >= Vn) tok = 2;
        if (tok < 0) tok = 0;
        const float* er = emb + (size_t)tok * Hn;
        for (int h = threadIdx.x; h < Hn; h += 256)
            g_x[b * Hn + h] = fmaxf(er[h], 0.0f);
        return;
    }
    __shared__ float sh[Hn];
    for (int i = threadIdx.x; i < Hn; i += 256) sh[i] = hprev[b * Hn + i];
    __syncthreads();
    int w = threadIdx.x >> 5, lane = threadIdx.x & 31;
    int idx = blockIdx.x * 8 + w;
    const float* row; float bv; float* dst;
    if (idx < Hn)        { row = wa_w2 + (size_t)idx * Hn; bv = wa_b2[idx]; dst = g_dqw + b * Hn + idx; }
    else if (idx < 2*Hn) { int o = idx - Hn; row = sa_w2 + (size_t)o * Hn; bv = sa_b2[o]; dst = g_dqs + b * Hn + o; }
    else                 { int j = idx - 2*Hn; row = w_hh + (size_t)j * Hn; bv = b_hh[j]; dst = g_gh + b * G3H + j; }
    const float4* r4 = (const float4*)row;
    const float4* s4 = (const float4*)sh;
    float s_ = 0.f;
#pragma unroll
    for (int k = 0; k < 4; k++) {
        float4 wv = r4[k * 32 + lane], hv = s4[k * 32 + lane];
        s_ += wv.x * hv.x + wv.y * hv.y + wv.z * hv.z + wv.w * hv.w;
    }
    s_ = warp_sum(s_);
    if (lane == 0) *dst = s_ + bv;
}

// ---------------- per-step K2: word scores ----------------
__global__ __launch_bounds__(256) void k_wordscore(const float* __restrict__ wa_v,
                                                   const float* __restrict__ wa_vb)
{
    int b = blockIdx.y;
    __shared__ float sq[Hn], sv[Hn];
    for (int i = threadIdx.x; i < Hn; i += 256) { sq[i] = g_dqw[b * Hn + i]; sv[i] = wa_v[i]; }
    __syncthreads();
    int w = threadIdx.x >> 5, lane = threadIdx.x & 31;
    int n = blockIdx.x * 8 + w;
    const float4* r4 = (const float4*)(g_wa_pre + ((size_t)(b * SW + n)) * Hn);
    const float4* q4 = (const float4*)sq;
    const float4* v4 = (const float4*)sv;
    float s_ = 0.f;
#pragma unroll
    for (int k = 0; k < 4; k++) {
        float4 p = r4[k * 32 + lane], q = q4[k * 32 + lane], vv = v4[k * 32 + lane];
        s_ += fast_tanh(p.x + q.x) * vv.x + fast_tanh(p.y + q.y) * vv.y +
              fast_tanh(p.z + q.z) * vv.z + fast_tanh(p.w + q.w) * vv.w;
    }
    s_ = warp_sum(s_);
    if (lane == 0) g_scw[b * SW + n] = s_ + wa_vb[0];
}

// ---------------- per-step K3: sent attn + softmaxes -> resc ----------------
// p_a_w is a softmax over W=32 WITHIN each sentence (warp = sentence).
__global__ __launch_bounds__(512) void k_attn(const float* __restrict__ sa_v,
                                              const float* __restrict__ sa_vb)
{
    int b = blockIdx.x;
    __shared__ float sq[Hn], sv[Hn], s_scs[Sn], s_ws[16];
    int tid = threadIdx.x;
    sq[tid] = g_dqs[b * Hn + tid];
    sv[tid] = sa_v[tid];
    __syncthreads();
    int s = tid >> 5, lane = tid & 31;
    {
        const float* row = g_sa_pre + (size_t)(b * Sn + s) * Hn;
        float ssum = 0.f;
#pragma unroll
        for (int k = 0; k < 16; k++) {
            int h = lane + 32 * k;
            ssum += fast_tanh(row[h] + sq[h]) * sv[h];
        }
        ssum = warp_sum(ssum);
        if (lane == 0) s_scs[s] = ssum + sa_vb[0];
    }
    __syncthreads();
    float smx = -1e30f;
#pragma unroll
    for (int i = 0; i < Sn; i++) smx = fmaxf(smx, s_scs[i]);
    float sden = 0.f;
#pragma unroll
    for (int i = 0; i < Sn; i++) sden += __expf(s_scs[i] - smx);
    float pas = __expf(s_scs[s] - smx) / sden;

    float v = g_scw[b * SW + tid];
    float wm = v;
#pragma unroll
    for (int o = 16; o; o >>= 1) wm = fmaxf(wm, __shfl_xor_sync(0xffffffffu, wm, o));
    float e = __expf(v - wm);
    float es = warp_sum(e);
    float num = (e / es) * pas;
    float bsum = warp_sum(num);
    if (lane == 0) s_ws[s] = bsum;
    __syncthreads();
    float tot = 0.f;
#pragma unroll
    for (int i = 0; i < 16; i++) tot += s_ws[i];
    g_resc[b * SW + tid] = num / (tot + 1e-10f);
}

// ---------------- per-step K4: ctx = resc @ word_flat ----------------
__global__ __launch_bounds__(128) void k_ctx(const float* __restrict__ word)
{
    int b = blockIdx.y;
    int h = blockIdx.x * 128 + threadIdx.x;
    __shared__ float sr[SW];
    for (int i = threadIdx.x; i < SW; i += 128) sr[i] = g_resc[b * SW + i];
    __syncthreads();
    const float* base = word + (size_t)b * SW * Hn + h;
    float a0 = 0.f, a1 = 0.f, a2 = 0.f, a3 = 0.f;
    for (int n = 0; n < SW; n += 4) {
        a0 += sr[n + 0] * base[(size_t)(n + 0) * Hn];
        a1 += sr[n + 1] * base[(size_t)(n + 1) * Hn];
        a2 += sr[n + 2] * base[(size_t)(n + 2) * Hn];
        a3 += sr[n + 3] * base[(size_t)(n + 3) * Hn];
    }
    g_ctx[b * Hn + h] = (a0 + a1) + (a2 + a3);
}

// ---------------- per-step K5: gi = [x,ctx] @ w_ih^T + b ----------------
__global__ __launch_bounds__(256) void k_gi(const float* __restrict__ w_ih,
                                            const float* __restrict__ b_ih)
{
    int b = blockIdx.y;
    __shared__ float sin_[2 * Hn];
    for (int i = threadIdx.x; i < Hn; i += 256) { sin_[i] = g_x[b * Hn + i]; sin_[Hn + i] = g_ctx[b * Hn + i]; }
    __syncthreads();
    int w = threadIdx.x >> 5, lane = threadIdx.x & 31;
    int j = blockIdx.x * 8 + w;
    const float4* r4 = (const float4*)(w_ih + (size_t)j * 2 * Hn);
    const float4* s4 = (const float4*)sin_;
    float s_ = 0.f;
#pragma unroll
    for (int k = 0; k < 8; k++) {
        float4 wv = r4[k * 32 + lane], hv = s4[k * 32 + lane];
        s_ += wv.x * hv.x + wv.y * hv.y + wv.z * hv.z + wv.w * hv.w;
    }
    s_ = warp_sum(s_);
    if (lane == 0) g_gi[b * G3H + j] = s_ + b_ih[j];
}

// ---------------- per-step K5b: gates -> h_new ----------------
__global__ __launch_bounds__(512) void k_gates(int t)
{
    int b = blockIdx.x; int hh = threadIdx.x;
    const float* hprev = g_h[t & 1];
    float* hnew = g_h[(t + 1) & 1];
    float ir = g_gi[b * G3H + hh], iz = g_gi[b * G3H + 512 + hh], in_ = g_gi[b * G3H + 1024 + hh];
    float hr = g_gh[b * G3H + hh], hz = g_gh[b * G3H + 512 + hh], hn = g_gh[b * G3H + 1024 + hh];
    float hp = hprev[b * Hn + hh];
    float r = fast_sigm(ir + hr);
    float z = fast_sigm(iz + hz);
    float n = fast_tanh(in_ + r * hn);
    hnew[b * Hn + hh] = (1.0f - z) * n + z * hp;
}

// ---------------- per-step K6: logits GEMV + sel hidden ----------------
#define LOGITS_BLOCKS 500
__global__ __launch_bounds__(256) void k_big(
    int t,
    const float* __restrict__ out_w, const float* __restrict__ out_b,
    const float* __restrict__ sel_w, const float* __restrict__ sel_b)
{
    const float* hnew = g_h[(t + 1) & 1];
    int w = threadIdx.x >> 5, lane = threadIdx.x & 31;
    if (blockIdx.x < LOGITS_BLOCKS) {
        int vbase = blockIdx.x * 64;
        int bq = w & 3, vg = w >> 2;
        int b0 = bq * 4;
        float4 hreg[4][4];
        const float4* h4 = (const float4*)hnew;
#pragma unroll
        for (int j = 0; j < 4; j++)
#pragma unroll
            for (int k = 0; k < 4; k++)
                hreg[j][k] = h4[(b0 + j) * (Hn / 4) + k * 32 + lane];
        const float4* w4 = (const float4*)out_w;
        for (int i = 0; i < 32; i++) {
            int v = vbase + vg + 2 * i;
            float4 wr[4];
#pragma unroll
            for (int k = 0; k < 4; k++) wr[k] = w4[(size_t)v * (Hn / 4) + k * 32 + lane];
            float acc[4];
#pragma unroll
            for (int j = 0; j < 4; j++) {
                float s_ = 0.f;
#pragma unroll
                for (int k = 0; k < 4; k++)
                    s_ += wr[k].x * hreg[j][k].x + wr[k].y * hreg[j][k].y +
                          wr[k].z * hreg[j][k].z + wr[k].w * hreg[j][k].w;
                acc[j] = s_;
            }
#pragma unroll
            for (int o = 16; o; o >>= 1)
#pragma unroll
                for (int j = 0; j < 4; j++)
                    acc[j] += __shfl_xor_sync(0xffffffffu, acc[j], o);
            if (lane < 4)
                g_logits[(size_t)(b0 + lane) * Vn + v] = acc[lane] + out_b[v];
        }
    } else {
        int sb = blockIdx.x - LOGITS_BLOCKS;
        int b = sb >> 6;
        int o = (sb & 63) * 8 + w;
        __shared__ float sin_[3 * Hn];
        for (int i = threadIdx.x; i < Hn; i += 256) {
            sin_[i] = hnew[b * Hn + i];
            sin_[Hn + i] = g_x[b * Hn + i];
            sin_[2 * Hn + i] = g_ctx[b * Hn + i];
        }
        __syncthreads();
        const float4* r4 = (const float4*)(sel_w + (size_t)o * 3 * Hn);
        const float4* s4 = (const float4*)sin_;
        float s_ = 0.f;
#pragma unroll
        for (int k = 0; k < 12; k++) {
            float4 wv = r4[k * 32 + lane], hv = s4[k * 32 + lane];
            s_ += wv.x * hv.x + wv.y * hv.y + wv.z * hv.z + wv.w * hv.w;
        }
        s_ = warp_sum(s_);
        if (lane == 0) g_selh[b * Hn + o] = fast_tanh(s_ + sel_b[o]);
    }
}

// ---------------- per-step K7: p_gen, softmax, p_final, scatter ----------------
__global__ __launch_bounds__(1024) void k_final(
    int t, float* __restrict__ out,
    const float* __restrict__ vs_w, const float* __restrict__ vs_b,
    const float* __restrict__ extra, const int* __restrict__ enc)
{
    int b = blockIdx.x; int tid = threadIdx.x;
    int wp = tid >> 5, lane = tid & 31;
    __shared__ float red[32];
    __shared__ float sh_pg, sh_mx, sh_sum;
    if (wp == 0) {
        float s_ = 0.f;
#pragma unroll
        for (int k = 0; k < 16; k++) { int h = lane + 32 * k; s_ += g_selh[b * Hn + h] * vs_w[h]; }
        s_ = warp_sum(s_);
        if (lane == 0) {
            float pg = fast_sigm(s_ + vs_b[0]);
            sh_pg = pg;
            out[(size_t)Bn * Tn * VEXT + Bn * Hn + b * Tn + t] = pg;
        }
    }
    __syncthreads();
    float pg = sh_pg;
    const float* lg = g_logits + (size_t)b * Vn;

    float mx = -1e30f;
    for (int v = tid; v < Vn; v += 1024) mx = fmaxf(mx, lg[v]);
#pragma unroll
    for (int o = 16; o; o >>= 1) mx = fmaxf(mx, __shfl_xor_sync(0xffffffffu, mx, o));
    if (lane == 0) red[wp] = mx;
    __syncthreads();
    if (wp == 0) {
        float m2 = red[lane];
#pragma unroll
        for (int o = 16; o; o >>= 1) m2 = fmaxf(m2, __shfl_xor_sync(0xffffffffu, m2, o));
        if (lane == 0) sh_mx = m2;
    }
    __syncthreads();
    mx = sh_mx;

    float ls = 0.f;
    for (int v = tid; v < Vn; v += 1024) ls += __expf(lg[v] - mx);
    ls = warp_sum(ls);
    if (lane == 0) red[wp] = ls;
    __syncthreads();
    if (wp == 0) {
        float s2 = warp_sum(red[lane]);
        if (lane == 0) sh_sum = s2;
    }
    __syncthreads();

    float scale = pg / sh_sum;
    float* base = out + ((size_t)b * Tn + t) * VEXT;
    for (int v = tid; v < Vn; v += 1024) base[v] = __expf(lg[v] - mx) * scale;
    if (tid < EXTRA) base[Vn + tid] = extra[b * EXTRA + tid];
    __syncthreads();

    if (tid < SW) {
        float val = (1.0f - pg) * g_resc[b * SW + tid];
        int idx = enc[b * SW + tid];
        if (idx >= VEXT || idx < 0) idx = 0;
        atomicAdd(base + idx, val);
    }
}

// ---------------- host ----------------
extern "C" void kernel_launch(void* const* d_in, const int* in_sizes, int n_in,
                              void* d_out, int out_size)
{
    (void)in_sizes; (void)n_in; (void)out_size;
    const float* word   = (const float*)d_in[0];
    const float* sent   = (const float*)d_in[1];
    const float* dinit  = (const float*)d_in[2];
    const float* extra  = (const float*)d_in[3];
    const int*   target = (const int*)  d_in[4];
    const int*   enc    = (const int*)  d_in[5];
    const float* emb    = (const float*)d_in[6];
    const float* w_ih   = (const float*)d_in[7];
    const float* w_hh   = (const float*)d_in[8];
    const float* b_ih   = (const float*)d_in[9];
    const float* b_hh   = (const float*)d_in[10];
    const float* out_w  = (const float*)d_in[11];
    const float* out_b  = (const float*)d_in[12];
    const float* wa_w1  = (const float*)d_in[13];
    const float* wa_b1  = (const float*)d_in[14];
    const float* wa_w2  = (const float*)d_in[15];
    const float* wa_b2  = (const float*)d_in[16];
    const float* wa_v   = (const float*)d_in[17];
    const float* wa_vb  = (const float*)d_in[18];
    const float* sa_w1  = (const float*)d_in[19];
    const float* sa_b1  = (const float*)d_in[20];
    const float* sa_w2  = (const float*)d_in[21];
    const float* sa_b2  = (const float*)d_in[22];
    const float* sa_v   = (const float*)d_in[23];
    const float* sa_vb  = (const float*)d_in[24];
    const float* sel_w  = (const float*)d_in[25];
    const float* sel_b  = (const float*)d_in[26];
    const float* vs_w   = (const float*)d_in[27];
    const float* vs_b   = (const float*)d_in[28];
    float* out = (float*)d_out;

    k_pre<<<Bn * SW / 16, 256>>>(word, wa_w1, wa_b1, 0);   // wa_pre: 8192 rows
    k_pre<<<Bn * Sn / 16, 256>>>(sent, sa_w1, sa_b1, 1);   // sa_pre: 256 rows
    k_init_h<<<(Bn * Hn + 255) / 256, 256>>>(dinit);

    for (int t = 0; t < Tn; t++) {
        k_step1<<<dim3(321, Bn), 256>>>(t, target, emb, wa_w2, wa_b2, sa_w2, sa_b2, w_hh, b_hh);
        k_wordscore<<<dim3(SW / 8, Bn), 256>>>(wa_v, wa_vb);
        k_attn<<<Bn, 512>>>(sa_v, sa_vb);
        k_ctx<<<dim3(Hn / 128, Bn), 128>>>(word);
        k_gi<<<dim3(G3H / 8, Bn), 256>>>(w_ih, b_ih);
        k_gates<<<Bn, 512>>>(t);
        k_big<<<LOGITS_BLOCKS + Bn * 64, 256>>>(t, out_w, out_b, sel_w, sel_b);
        k_final<<<Bn, 1024>>>(t, out, vs_w, vs_b, extra, enc);
    }
    k_out_h<<<(Bn * Hn + 255) / 256, 256>>>(out);
}

// round 8
// speedup vs baseline: 1.0025x; 1.0025x over previous
#include <cuda_runtime.h>

#define Bn 16
#define Sn 16
#define Wn 32
#define Hn 512
#define Vn 32000
#define EXTRA 100
#define Tn 64
#define BOSTOK 1
#define SW 512          // Sn*Wn
#define VEXT 32100
#define G3H 1536

// ---------------- scratch (device globals; no allocation) ----------------
__device__ float g_wa_pre[Bn*SW*Hn];     // 16.8 MB
__device__ float g_sa_pre[Bn*Sn*Hn];
__device__ float g_x[Bn*Hn];
__device__ float g_dqw[Bn*Hn];
__device__ float g_dqs[Bn*Hn];
__device__ float g_scw[Bn*SW];
__device__ float g_resc[Bn*SW];
__device__ float g_ctx[Bn*Hn];
__device__ float g_gh[Bn*G3H];
__device__ float g_gi[Bn*G3H];
__device__ float g_selh[Bn*Hn];
__device__ float g_h[2][Bn*Hn];
__device__ float g_logits[(size_t)Bn*Vn]; // 2 MB

// ---------------- helpers ----------------
__device__ __forceinline__ float fast_tanh(float x) {
    float ax = fabsf(x);
    float t = __expf(-2.0f * ax);
    float r = (1.0f - t) / (1.0f + t);
    return copysignf(r, x);
}
__device__ __forceinline__ float fast_sigm(float x) {
    return 1.0f / (1.0f + __expf(-x));
}
__device__ __forceinline__ float warp_sum(float v) {
#pragma unroll
    for (int o = 16; o; o >>= 1) v += __shfl_xor_sync(0xffffffffu, v, o);
    return v;
}

// ---------------- one-time: pre = A @ W^T + b  (rows x 512, K=512) ----------
// block: 256 thr (8 warps), 16 A-rows in smem; warp holds 4 weight rows in regs
__global__ __launch_bounds__(256) void k_pre(const float* __restrict__ A,
                                             const float* __restrict__ Wt,
                                             const float* __restrict__ bias,
                                             int dst_sel)
{
    float* outp = dst_sel ? g_sa_pre : g_wa_pre;
    __shared__ float sh[16 * Hn];
    int r0 = blockIdx.x * 16;
    const float4* A4 = (const float4*)(A + (size_t)r0 * Hn);
    float4* sh4 = (float4*)sh;
    for (int i = threadIdx.x; i < 16 * Hn / 4; i += 256) sh4[i] = A4[i];
    __syncthreads();
    int w = threadIdx.x >> 5, lane = threadIdx.x & 31;
    const float4* W4 = (const float4*)Wt;
    for (int g = w; g < 128; g += 8) {
        int o0 = g * 4;
        float4 wr[4][4];
#pragma unroll
        for (int j = 0; j < 4; j++)
#pragma unroll
            for (int k = 0; k < 4; k++)
                wr[j][k] = W4[(size_t)(o0 + j) * (Hn / 4) + k * 32 + lane];
        for (int r = 0; r < 16; r++) {
            float4 a[4];
#pragma unroll
            for (int k = 0; k < 4; k++) a[k] = sh4[r * (Hn / 4) + k * 32 + lane];
            float acc[4];
#pragma unroll
            for (int j = 0; j < 4; j++) {
                float s_ = 0.f;
#pragma unroll
                for (int k = 0; k < 4; k++)
                    s_ += wr[j][k].x * a[k].x + wr[j][k].y * a[k].y +
                          wr[j][k].z * a[k].z + wr[j][k].w * a[k].w;
                acc[j] = s_;
            }
#pragma unroll
            for (int o = 16; o; o >>= 1)
#pragma unroll
                for (int j = 0; j < 4; j++)
                    acc[j] += __shfl_xor_sync(0xffffffffu, acc[j], o);
            if (lane < 4)
                outp[(size_t)(r0 + r) * Hn + o0 + lane] = acc[lane] + bias[o0 + lane];
        }
    }
}

__global__ void k_init_h(const float* __restrict__ src) {
    int i = blockIdx.x * 256 + threadIdx.x;
    if (i < Bn * Hn) g_h[0][i] = src[i];
}
__global__ void k_out_h(float* __restrict__ out) {
    int i = blockIdx.x * 256 + threadIdx.x;
    if (i < Bn * Hn) out[(size_t)Bn * Tn * VEXT + i] = g_h[0][i];
}

// ---------------- per-step K1: x, dq_w, dq_s, gh ----------------
// grid (321, 16): bx<320 -> warp-per-dot (2560 outputs/b); bx==320 -> x gather
__global__ __launch_bounds__(256) void k_step1(
    int t, const int* __restrict__ target, const float* __restrict__ emb,
    const float* __restrict__ wa_w2, const float* __restrict__ wa_b2,
    const float* __restrict__ sa_w2, const float* __restrict__ sa_b2,
    const float* __restrict__ w_hh, const float* __restrict__ b_hh)
{
    int b = blockIdx.y;
    const float* hprev = g_h[t & 1];
    if (blockIdx.x == 320) {
        int tok = (t == 0) ? BOSTOK : target[b * Tn + t - 1];
        if (tok >= Vn) tok = 2;
        if (tok < 0) tok = 0;
        const float* er = emb + (size_t)tok * Hn;
        for (int h = threadIdx.x; h < Hn; h += 256)
            g_x[b * Hn + h] = fmaxf(er[h], 0.0f);
        return;
    }
    __shared__ float sh[Hn];
    for (int i = threadIdx.x; i < Hn; i += 256) sh[i] = hprev[b * Hn + i];
    __syncthreads();
    int w = threadIdx.x >> 5, lane = threadIdx.x & 31;
    int idx = blockIdx.x * 8 + w;
    const float* row; float bv; float* dst;
    if (idx < Hn)        { row = wa_w2 + (size_t)idx * Hn; bv = wa_b2[idx]; dst = g_dqw + b * Hn + idx; }
    else if (idx < 2*Hn) { int o = idx - Hn; row = sa_w2 + (size_t)o * Hn; bv = sa_b2[o]; dst = g_dqs + b * Hn + o; }
    else                 { int j = idx - 2*Hn; row = w_hh + (size_t)j * Hn; bv = b_hh[j]; dst = g_gh + b * G3H + j; }
    const float4* r4 = (const float4*)row;
    const float4* s4 = (const float4*)sh;
    float s_ = 0.f;
#pragma unroll
    for (int k = 0; k < 4; k++) {
        float4 wv = r4[k * 32 + lane], hv = s4[k * 32 + lane];
        s_ += wv.x * hv.x + wv.y * hv.y + wv.z * hv.z + wv.w * hv.w;
    }
    s_ = warp_sum(s_);
    if (lane == 0) *dst = s_ + bv;
}

// ---------------- per-step K2: word scores ----------------
__global__ __launch_bounds__(256) void k_wordscore(const float* __restrict__ wa_v,
                                                   const float* __restrict__ wa_vb)
{
    int b = blockIdx.y;
    __shared__ float sq[Hn], sv[Hn];
    for (int i = threadIdx.x; i < Hn; i += 256) { sq[i] = g_dqw[b * Hn + i]; sv[i] = wa_v[i]; }
    __syncthreads();
    int w = threadIdx.x >> 5, lane = threadIdx.x & 31;
    int n = blockIdx.x * 8 + w;
    const float4* r4 = (const float4*)(g_wa_pre + ((size_t)(b * SW + n)) * Hn);
    const float4* q4 = (const float4*)sq;
    const float4* v4 = (const float4*)sv;
    float s_ = 0.f;
#pragma unroll
    for (int k = 0; k < 4; k++) {
        float4 p = r4[k * 32 + lane], q = q4[k * 32 + lane], vv = v4[k * 32 + lane];
        s_ += fast_tanh(p.x + q.x) * vv.x + fast_tanh(p.y + q.y) * vv.y +
              fast_tanh(p.z + q.z) * vv.z + fast_tanh(p.w + q.w) * vv.w;
    }
    s_ = warp_sum(s_);
    if (lane == 0) g_scw[b * SW + n] = s_ + wa_vb[0];
}

// ---------------- per-step K3: sent attn + softmaxes -> resc ----------------
// p_a_w is a softmax over W=32 WITHIN each sentence (warp = sentence).
__global__ __launch_bounds__(512) void k_attn(const float* __restrict__ sa_v,
                                              const float* __restrict__ sa_vb)
{
    int b = blockIdx.x;
    __shared__ float sq[Hn], sv[Hn], s_scs[Sn], s_ws[16];
    int tid = threadIdx.x;
    sq[tid] = g_dqs[b * Hn + tid];
    sv[tid] = sa_v[tid];
    __syncthreads();
    int s = tid >> 5, lane = tid & 31;
    {
        const float* row = g_sa_pre + (size_t)(b * Sn + s) * Hn;
        float ssum = 0.f;
#pragma unroll
        for (int k = 0; k < 16; k++) {
            int h = lane + 32 * k;
            ssum += fast_tanh(row[h] + sq[h]) * sv[h];
        }
        ssum = warp_sum(ssum);
        if (lane == 0) s_scs[s] = ssum + sa_vb[0];
    }
    __syncthreads();
    float smx = -1e30f;
#pragma unroll
    for (int i = 0; i < Sn; i++) smx = fmaxf(smx, s_scs[i]);
    float sden = 0.f;
#pragma unroll
    for (int i = 0; i < Sn; i++) sden += __expf(s_scs[i] - smx);
    float pas = __expf(s_scs[s] - smx) / sden;

    float v = g_scw[b * SW + tid];
    float wm = v;
#pragma unroll
    for (int o = 16; o; o >>= 1) wm = fmaxf(wm, __shfl_xor_sync(0xffffffffu, wm, o));
    float e = __expf(v - wm);
    float es = warp_sum(e);
    float num = (e / es) * pas;
    float bsum = warp_sum(num);
    if (lane == 0) s_ws[s] = bsum;
    __syncthreads();
    float tot = 0.f;
#pragma unroll
    for (int i = 0; i < 16; i++) tot += s_ws[i];
    g_resc[b * SW + tid] = num / (tot + 1e-10f);
}

// ---------------- per-step K4: ctx = resc @ word_flat ----------------
__global__ __launch_bounds__(128) void k_ctx(const float* __restrict__ word)
{
    int b = blockIdx.y;
    int h = blockIdx.x * 128 + threadIdx.x;
    __shared__ float sr[SW];
    for (int i = threadIdx.x; i < SW; i += 128) sr[i] = g_resc[b * SW + i];
    __syncthreads();
    const float* base = word + (size_t)b * SW * Hn + h;
    float a0 = 0.f, a1 = 0.f, a2 = 0.f, a3 = 0.f;
    for (int n = 0; n < SW; n += 4) {
        a0 += sr[n + 0] * base[(size_t)(n + 0) * Hn];
        a1 += sr[n + 1] * base[(size_t)(n + 1) * Hn];
        a2 += sr[n + 2] * base[(size_t)(n + 2) * Hn];
        a3 += sr[n + 3] * base[(size_t)(n + 3) * Hn];
    }
    g_ctx[b * Hn + h] = (a0 + a1) + (a2 + a3);
}

// ---------------- per-step K5: gi = [x,ctx] @ w_ih^T + b ----------------
__global__ __launch_bounds__(256) void k_gi(const float* __restrict__ w_ih,
                                            const float* __restrict__ b_ih)
{
    int b = blockIdx.y;
    __shared__ float sin_[2 * Hn];
    for (int i = threadIdx.x; i < Hn; i += 256) { sin_[i] = g_x[b * Hn + i]; sin_[Hn + i] = g_ctx[b * Hn + i]; }
    __syncthreads();
    int w = threadIdx.x >> 5, lane = threadIdx.x & 31;
    int j = blockIdx.x * 8 + w;
    const float4* r4 = (const float4*)(w_ih + (size_t)j * 2 * Hn);
    const float4* s4 = (const float4*)sin_;
    float s_ = 0.f;
#pragma unroll
    for (int k = 0; k < 8; k++) {
        float4 wv = r4[k * 32 + lane], hv = s4[k * 32 + lane];
        s_ += wv.x * hv.x + wv.y * hv.y + wv.z * hv.z + wv.w * hv.w;
    }
    s_ = warp_sum(s_);
    if (lane == 0) g_gi[b * G3H + j] = s_ + b_ih[j];
}

// ---------------- per-step K5b: gates -> h_new ----------------
__global__ __launch_bounds__(512) void k_gates(int t)
{
    int b = blockIdx.x; int hh = threadIdx.x;
    const float* hprev = g_h[t & 1];
    float* hnew = g_h[(t + 1) & 1];
    float ir = g_gi[b * G3H + hh], iz = g_gi[b * G3H + 512 + hh], in_ = g_gi[b * G3H + 1024 + hh];
    float hr = g_gh[b * G3H + hh], hz = g_gh[b * G3H + 512 + hh], hn = g_gh[b * G3H + 1024 + hh];
    float hp = hprev[b * Hn + hh];
    float r = fast_sigm(ir + hr);
    float z = fast_sigm(iz + hz);
    float n = fast_tanh(in_ + r * hn);
    hnew[b * Hn + hh] = (1.0f - z) * n + z * hp;
}

// ---------------- per-step K6: logits GEMV + sel hidden ----------------
#define LOGITS_BLOCKS 500
__global__ __launch_bounds__(256) void k_big(
    int t,
    const float* __restrict__ out_w, const float* __restrict__ out_b,
    const float* __restrict__ sel_w, const float* __restrict__ sel_b)
{
    const float* hnew = g_h[(t + 1) & 1];
    int w = threadIdx.x >> 5, lane = threadIdx.x & 31;
    if (blockIdx.x < LOGITS_BLOCKS) {
        int vbase = blockIdx.x * 64;
        int bq = w & 3, vg = w >> 2;
        int b0 = bq * 4;
        float4 hreg[4][4];
        const float4* h4 = (const float4*)hnew;
#pragma unroll
        for (int j = 0; j < 4; j++)
#pragma unroll
            for (int k = 0; k < 4; k++)
                hreg[j][k] = h4[(b0 + j) * (Hn / 4) + k * 32 + lane];
        const float4* w4 = (const float4*)out_w;
        for (int i = 0; i < 32; i++) {
            int v = vbase + vg + 2 * i;
            float4 wr[4];
#pragma unroll
            for (int k = 0; k < 4; k++) wr[k] = w4[(size_t)v * (Hn / 4) + k * 32 + lane];
            float acc[4];
#pragma unroll
            for (int j = 0; j < 4; j++) {
                float s_ = 0.f;
#pragma unroll
                for (int k = 0; k < 4; k++)
                    s_ += wr[k].x * hreg[j][k].x + wr[k].y * hreg[j][k].y +
                          wr[k].z * hreg[j][k].z + wr[k].w * hreg[j][k].w;
                acc[j] = s_;
            }
#pragma unroll
            for (int o = 16; o; o >>= 1)
#pragma unroll
                for (int j = 0; j < 4; j++)
                    acc[j] += __shfl_xor_sync(0xffffffffu, acc[j], o);
            if (lane < 4)
                g_logits[(size_t)(b0 + lane) * Vn + v] = acc[lane] + out_b[v];
        }
    } else {
        int sb = blockIdx.x - LOGITS_BLOCKS;
        int b = sb >> 6;
        int o = (sb & 63) * 8 + w;
        __shared__ float sin_[3 * Hn];
        for (int i = threadIdx.x; i < Hn; i += 256) {
            sin_[i] = hnew[b * Hn + i];
            sin_[Hn + i] = g_x[b * Hn + i];
            sin_[2 * Hn + i] = g_ctx[b * Hn + i];
        }
        __syncthreads();
        const float4* r4 = (const float4*)(sel_w + (size_t)o * 3 * Hn);
        const float4* s4 = (const float4*)sin_;
        float s_ = 0.f;
#pragma unroll
        for (int k = 0; k < 12; k++) {
            float4 wv = r4[k * 32 + lane], hv = s4[k * 32 + lane];
            s_ += wv.x * hv.x + wv.y * hv.y + wv.z * hv.z + wv.w * hv.w;
        }
        s_ = warp_sum(s_);
        if (lane == 0) g_selh[b * Hn + o] = fast_tanh(s_ + sel_b[o]);
    }
}

// ---------------- per-step K7: p_gen, softmax, p_final, scatter ----------------
__global__ __launch_bounds__(1024) void k_final(
    int t, float* __restrict__ out,
    const float* __restrict__ vs_w, const float* __restrict__ vs_b,
    const float* __restrict__ extra, const int* __restrict__ enc)
{
    int b = blockIdx.x; int tid = threadIdx.x;
    int wp = tid >> 5, lane = tid & 31;
    __shared__ float red[32];
    __shared__ float sh_pg, sh_mx, sh_sum;
    if (wp == 0) {
        float s_ = 0.f;
#pragma unroll
        for (int k = 0; k < 16; k++) { int h = lane + 32 * k; s_ += g_selh[b * Hn + h] * vs_w[h]; }
        s_ = warp_sum(s_);
        if (lane == 0) {
            float pg = fast_sigm(s_ + vs_b[0]);
            sh_pg = pg;
            out[(size_t)Bn * Tn * VEXT + Bn * Hn + b * Tn + t] = pg;
        }
    }
    __syncthreads();
    float pg = sh_pg;
    const float* lg = g_logits + (size_t)b * Vn;

    float mx = -1e30f;
    for (int v = tid; v < Vn; v += 1024) mx = fmaxf(mx, lg[v]);
#pragma unroll
    for (int o = 16; o; o >>= 1) mx = fmaxf(mx, __shfl_xor_sync(0xffffffffu, mx, o));
    if (lane == 0) red[wp] = mx;
    __syncthreads();
    if (wp == 0) {
        float m2 = red[lane];
#pragma unroll
        for (int o = 16; o; o >>= 1) m2 = fmaxf(m2, __shfl_xor_sync(0xffffffffu, m2, o));
        if (lane == 0) sh_mx = m2;
    }
    __syncthreads();
    mx = sh_mx;

    float ls = 0.f;
    for (int v = tid; v < Vn; v += 1024) ls += __expf(lg[v] - mx);
    ls = warp_sum(ls);
    if (lane == 0) red[wp] = ls;
    __syncthreads();
    if (wp == 0) {
        float s2 = warp_sum(red[lane]);
        if (lane == 0) sh_sum = s2;
    }
    __syncthreads();

    float scale = pg / sh_sum;
    float* base = out + ((size_t)b * Tn + t) * VEXT;
    for (int v = tid; v < Vn; v += 1024) base[v] = __expf(lg[v] - mx) * scale;
    if (tid < EXTRA) base[Vn + tid] = extra[b * EXTRA + tid];
    __syncthreads();

    if (tid < SW) {
        float val = (1.0f - pg) * g_resc[b * SW + tid];
        int idx = enc[b * SW + tid];
        if (idx >= VEXT || idx < 0) idx = 0;
        atomicAdd(base + idx, val);
    }
}

// ---------------- host ----------------
extern "C" void kernel_launch(void* const* d_in, const int* in_sizes, int n_in,
                              void* d_out, int out_size)
{
    (void)in_sizes; (void)n_in; (void)out_size;
    const float* word   = (const float*)d_in[0];
    const float* sent   = (const float*)d_in[1];
    const float* dinit  = (const float*)d_in[2];
    const float* extra  = (const float*)d_in[3];
    const int*   target = (const int*)  d_in[4];
    const int*   enc    = (const int*)  d_in[5];
    const float* emb    = (const float*)d_in[6];
    const float* w_ih   = (const float*)d_in[7];
    const float* w_hh   = (const float*)d_in[8];
    const float* b_ih   = (const float*)d_in[9];
    const float* b_hh   = (const float*)d_in[10];
    const float* out_w  = (const float*)d_in[11];
    const float* out_b  = (const float*)d_in[12];
    const float* wa_w1  = (const float*)d_in[13];
    const float* wa_b1  = (const float*)d_in[14];
    const float* wa_w2  = (const float*)d_in[15];
    const float* wa_b2  = (const float*)d_in[16];
    const float* wa_v   = (const float*)d_in[17];
    const float* wa_vb  = (const float*)d_in[18];
    const float* sa_w1  = (const float*)d_in[19];
    const float* sa_b1  = (const float*)d_in[20];
    const float* sa_w2  = (const float*)d_in[21];
    const float* sa_b2  = (const float*)d_in[22];
    const float* sa_v   = (const float*)d_in[23];
    const float* sa_vb  = (const float*)d_in[24];
    const float* sel_w  = (const float*)d_in[25];
    const float* sel_b  = (const float*)d_in[26];
    const float* vs_w   = (const float*)d_in[27];
    const float* vs_b   = (const float*)d_in[28];
    float* out = (float*)d_out;

    k_pre<<<Bn * SW / 16, 256>>>(word, wa_w1, wa_b1, 0);   // wa_pre: 8192 rows
    k_pre<<<Bn * Sn / 16, 256>>>(sent, sa_w1, sa_b1, 1);   // sa_pre: 256 rows
    k_init_h<<<(Bn * Hn + 255) / 256, 256>>>(dinit);

    for (int t = 0; t < Tn; t++) {
        k_step1<<<dim3(321, Bn), 256>>>(t, target, emb, wa_w2, wa_b2, sa_w2, sa_b2, w_hh, b_hh);
        k_wordscore<<<dim3(SW / 8, Bn), 256>>>(wa_v, wa_vb);
        k_attn<<<Bn, 512>>>(sa_v, sa_vb);
        k_ctx<<<dim3(Hn / 128, Bn), 128>>>(word);
        k_gi<<<dim3(G3H / 8, Bn), 256>>>(w_ih, b_ih);
        k_gates<<<Bn, 512>>>(t);
        k_big<<<LOGITS_BLOCKS + Bn * 64, 256>>>(t, out_w, out_b, sel_w, sel_b);
        k_final<<<Bn, 1024>>>(t, out, vs_w, vs_b, extra, enc);
    }
    k_out_h<<<(Bn * Hn + 255) / 256, 256>>>(out);
}